// round 4
// baseline (speedup 1.0000x reference)
#include <cuda_runtime.h>
#include <cuda_fp16.h>

#define B_   4
#define CIN  256
#define CO_  64
#define N_   576   // 24*24
#define CV_  256

// Scratch (device globals — no allocation allowed)
__device__ float g_kp[B_ * N_ * CO_];          // (B, Nk, CO)
__device__ float g_qp[B_ * N_ * CO_];          // (B, Nq, CO)
__device__ float g_attn[B_ * N_ * N_];         // (B, Nk, Nq)

// ---------- packed helpers ----------
__device__ __forceinline__ unsigned long long pack2(float lo, float hi) {
    unsigned long long r;
    asm("mov.b64 %0, {%1, %2};" : "=l"(r) : "f"(lo), "f"(hi));
    return r;
}
__device__ __forceinline__ void unpack2(unsigned long long v, float& lo, float& hi) {
    asm("mov.b64 {%0, %1}, %2;" : "=f"(lo), "=f"(hi) : "l"(v));
}
__device__ __forceinline__ unsigned long long ffma2(unsigned long long a,
                                                    unsigned long long b,
                                                    unsigned long long c) {
    unsigned long long d;
    asm("fma.rn.f32x2 %0, %1, %2, %3;" : "=l"(d) : "l"(a), "l"(b), "l"(c));
    return d;
}
__device__ __forceinline__ float tanhfast(float x) {
    float y;
    asm("tanh.approx.f32 %0, %1;" : "=f"(y) : "f"(x));
    return y;
}
__device__ __forceinline__ unsigned tanh_h2(unsigned x) {
    unsigned y;
    asm("tanh.approx.f16x2 %0, %1;" : "=r"(y) : "r"(x));
    return y;
}
__device__ __forceinline__ __half2 u2h(unsigned u) { return *(__half2*)&u; }
__device__ __forceinline__ unsigned h2u(__half2 h) { return *(unsigned*)&h; }

// ============================================================================
// Kernel A: projections. out[b,n,c] = sum_ch X[b,ch,n]*W[c,ch] + bias[c]
// GEMM-tiled: grid (18 n-tiles of 32, B, 2), 256 thr; thread = 2c x 4n.
// Inner loop: 1 LDS.128 (x as packed f32x2) + 1 LDS.64 (w) + 4 FFMA2.
// ============================================================================
__global__ void __launch_bounds__(256) proj_kernel(
    const float* __restrict__ key, const float* __restrict__ query,
    const float* __restrict__ Wk,  const float* __restrict__ bk,
    const float* __restrict__ Wq,  const float* __restrict__ bq)
{
    const int kind = blockIdx.z;
    const float* X    = kind ? query : key;    // (B, CIN, N)
    const float* W    = kind ? Wq    : Wk;     // (CO, CIN)
    const float* bias = kind ? bq    : bk;
    float* outp       = kind ? g_qp  : g_kp;   // (B, N, CO)

    const int b  = blockIdx.y;
    const int n0 = blockIdx.x * 32;

    __shared__ __align__(16) float sX[32][32];   // [ch][n], rows 128B
    __shared__ __align__(16) float sW[32][66];   // [ch][c], even stride -> 8B aligned

    const int t   = threadIdx.x;
    const int ng  = t & 7;          // n = ng*4 .. +3
    const int cgr = t >> 3;         // c = cgr*2, cgr 0..31
    const int c   = cgr * 2;

    unsigned long long a00 = 0ull, a01 = 0ull, a10 = 0ull, a11 = 0ull;

    for (int ch0 = 0; ch0 < CIN; ch0 += 32) {
        // stage X: 32ch x 32n (coalesced over n)
        {
            const int n  = t & 31;
            const int cb = t >> 5;
            #pragma unroll
            for (int i = 0; i < 4; i++) {
                const int ch = cb + i * 8;
                sX[ch][n] = X[((size_t)(b * CIN + ch0 + ch)) * N_ + n0 + n];
            }
        }
        // stage W transposed: sW[ch][c] (coalesced LDG over ch)
        {
            const int chx = t & 31;
            const int cb  = t >> 5;
            #pragma unroll
            for (int i = 0; i < 8; i++) {
                const int cr = cb + i * 8;
                sW[chx][cr] = W[cr * CIN + ch0 + chx];
            }
        }
        __syncthreads();

        #pragma unroll 8
        for (int ch = 0; ch < 32; ch++) {
            const ulonglong2 xp = *(const ulonglong2*)&sX[ch][ng * 4]; // 2 n-pairs
            const float2     w2 = *(const float2*)&sW[ch][c];          // 2 c
            const unsigned long long ww0 = pack2(w2.x, w2.x);
            const unsigned long long ww1 = pack2(w2.y, w2.y);
            a00 = ffma2(xp.x, ww0, a00);
            a01 = ffma2(xp.y, ww0, a01);
            a10 = ffma2(xp.x, ww1, a10);
            a11 = ffma2(xp.y, ww1, a11);
        }
        __syncthreads();
    }

    const float bv0 = bias[c];
    const float bv1 = bias[c + 1];
    float x0, x1, x2, x3, y0, y1, y2, y3;
    unpack2(a00, x0, x1);   // c,   n0..n1
    unpack2(a01, x2, x3);   // c,   n2..n3
    unpack2(a10, y0, y1);   // c+1, n0..n1
    unpack2(a11, y2, y3);   // c+1, n2..n3

    const int n = n0 + ng * 4;
    float* op = outp + ((size_t)b * N_ + n) * CO_ + c;
    *(float2*)(op + 0 * CO_) = make_float2(x0 + bv0, y0 + bv1);
    *(float2*)(op + 1 * CO_) = make_float2(x1 + bv0, y1 + bv1);
    *(float2*)(op + 2 * CO_) = make_float2(x2 + bv0, y2 + bv1);
    *(float2*)(op + 3 * CO_) = make_float2(x3 + bv0, y3 + bv1);
}

// ============================================================================
// Kernel B: attn[b,k,q] = sigmoid( bf + sum_c tanh(kp[k,c]+qp[q,c])*wf[c] )
// grid (18 q-tiles, 18 k-tiles, B), 256 thr. Thread = 4k x 1q (q = lane).
// Tiles converted to half2 ONCE at smem load; hot loop = HADD2+tanh.f16x2+HFMA2.
// ============================================================================
__global__ void __launch_bounds__(256) attn_kernel(
    const float* __restrict__ wf, const float* __restrict__ bfp)
{
    const int b  = blockIdx.z;
    const int k0 = blockIdx.y * 32;
    const int q0 = blockIdx.x * 32;

    __shared__ unsigned skh[32][34];   // half2 pairs over c
    __shared__ unsigned sqh[32][34];
    __shared__ unsigned swh[32];

    const int t = threadIdx.x;
    #pragma unroll
    for (int j = 0; j < 4; j++) {
        const int idx = t + j * 256;       // 1024 half2 per tile
        const int r  = idx >> 5;
        const int cc = idx & 31;
        const float2 kv = *(const float2*)&g_kp[((size_t)b * N_ + k0 + r) * CO_ + cc * 2];
        const float2 qv = *(const float2*)&g_qp[((size_t)b * N_ + q0 + r) * CO_ + cc * 2];
        skh[r][cc] = h2u(__floats2half2_rn(kv.x, kv.y));
        sqh[r][cc] = h2u(__floats2half2_rn(qv.x, qv.y));
    }
    if (t < 32) {
        const float2 w = *(const float2*)&wf[t * 2];
        swh[t] = h2u(__floats2half2_rn(w.x, w.y));
    }
    __syncthreads();

    const int q  = t & 31;            // lane -> CF q loads, coalesced STG
    const int k4 = (t >> 5) * 4;      // 4 k's (warp-constant -> broadcast)

    __half2 ae[4], ao[4];
    #pragma unroll
    for (int i = 0; i < 4; i++) { ae[i] = __float2half2_rn(0.f); ao[i] = ae[i]; }

    const unsigned* __restrict__ qrow = sqh[q];

    #pragma unroll
    for (int cc = 0; cc < 32; cc += 2) {
        const uint2 qv = *(const uint2*)&qrow[cc];
        const uint2 wv = *(const uint2*)&swh[cc];
        #pragma unroll
        for (int i = 0; i < 4; i++) {
            const uint2 kv = *(const uint2*)&skh[k4 + i][cc];
            const unsigned t0 = tanh_h2(h2u(__hadd2(u2h(kv.x), u2h(qv.x))));
            const unsigned t1 = tanh_h2(h2u(__hadd2(u2h(kv.y), u2h(qv.y))));
            ae[i] = __hfma2(u2h(t0), u2h(wv.x), ae[i]);
            ao[i] = __hfma2(u2h(t1), u2h(wv.y), ao[i]);
        }
    }

    const float bf = __ldg(bfp);
    #pragma unroll
    for (int i = 0; i < 4; i++) {
        const float2 fe = __half22float2(ae[i]);
        const float2 fo = __half22float2(ao[i]);
        const float s = bf + ((fe.x + fe.y) + (fo.x + fo.y));
        g_attn[((size_t)b * N_ + k0 + k4 + i) * N_ + q0 + q] =
            fmaf(0.5f, tanhfast(0.5f * s), 0.5f);   // sigmoid
    }
}

// ============================================================================
// Kernel C: out[b,c,q] = sum_k value[b,c,k] * attn[b,k,q]
// grid (9 q-tiles of 64, 4 c-tiles of 64, B), 256 thr; thread = 4c x 4q.
// ============================================================================
__global__ void __launch_bounds__(256) out_kernel(
    const float* __restrict__ value, float* __restrict__ out)
{
    const int b  = blockIdx.z;
    const int c0 = blockIdx.y * 64;
    const int q0 = blockIdx.x * 64;

    __shared__ __align__(16) float sV[32][68];   // [k][c]
    __shared__ __align__(16) float sA[32][68];   // [k][q]

    const int t  = threadIdx.x;
    const int qg = t & 15;          // q = qg*4 .. +3
    const int cg = t >> 4;          // c = cg*4 .. +3

    unsigned long long acc[4][2];
    #pragma unroll
    for (int i = 0; i < 4; i++) { acc[i][0] = 0ull; acc[i][1] = 0ull; }

    for (int k0 = 0; k0 < N_; k0 += 32) {
        {   // V tile 64c x 32k, transpose into sV[k][c] (coalesced over k)
            const int kk = t & 31;
            const int cb = t >> 5;
            #pragma unroll
            for (int i = 0; i < 8; i++) {
                const int cr = cb + i * 8;
                sV[kk][cr] = value[((size_t)(b * CV_ + c0 + cr)) * N_ + k0 + kk];
            }
        }
        {   // A tile 32k x 64q (coalesced over q)
            const int q  = t & 63;
            const int kb = t >> 6;
            #pragma unroll
            for (int i = 0; i < 8; i++) {
                const int kr = kb + i * 4;
                sA[kr][q] = g_attn[((size_t)b * N_ + k0 + kr) * N_ + q0 + q];
            }
        }
        __syncthreads();

        #pragma unroll 8
        for (int kk = 0; kk < 32; kk++) {
            const float4 v4 = *(const float4*)&sV[kk][cg * 4];         // 4 c
            const ulonglong2 a2 = *(const ulonglong2*)&sA[kk][qg * 4]; // 4 q
            const unsigned long long v0 = pack2(v4.x, v4.x);
            const unsigned long long v1 = pack2(v4.y, v4.y);
            const unsigned long long v2 = pack2(v4.z, v4.z);
            const unsigned long long v3 = pack2(v4.w, v4.w);
            acc[0][0] = ffma2(v0, a2.x, acc[0][0]);
            acc[0][1] = ffma2(v0, a2.y, acc[0][1]);
            acc[1][0] = ffma2(v1, a2.x, acc[1][0]);
            acc[1][1] = ffma2(v1, a2.y, acc[1][1]);
            acc[2][0] = ffma2(v2, a2.x, acc[2][0]);
            acc[2][1] = ffma2(v2, a2.y, acc[2][1]);
            acc[3][0] = ffma2(v3, a2.x, acc[3][0]);
            acc[3][1] = ffma2(v3, a2.y, acc[3][1]);
        }
        __syncthreads();
    }

    #pragma unroll
    for (int i = 0; i < 4; i++) {
        float o0, o1, o2, o3;
        unpack2(acc[i][0], o0, o1);
        unpack2(acc[i][1], o2, o3);
        *(float4*)&out[((size_t)(b * CV_ + c0 + cg * 4 + i)) * N_ + q0 + qg * 4] =
            make_float4(o0, o1, o2, o3);
    }
}

// ============================================================================
extern "C" void kernel_launch(void* const* d_in, const int* in_sizes, int n_in,
                              void* d_out, int out_size)
{
    const float* key   = (const float*)d_in[0];
    const float* query = (const float*)d_in[1];
    const float* value = (const float*)d_in[2];
    const float* Wk    = (const float*)d_in[3];
    const float* bk    = (const float*)d_in[4];
    const float* Wq    = (const float*)d_in[5];
    const float* bq    = (const float*)d_in[6];
    const float* wf    = (const float*)d_in[7];
    const float* bf    = (const float*)d_in[8];
    float* out = (float*)d_out;

    proj_kernel<<<dim3(N_ / 32, B_, 2), 256>>>(key, query, Wk, bk, Wq, bq);
    attn_kernel<<<dim3(N_ / 32, N_ / 32, B_), 256>>>(wf, bf);
    out_kernel<<<dim3(N_ / 64, CV_ / 64, B_), 256>>>(value, out);
}

// round 5
// speedup vs baseline: 1.1168x; 1.1168x over previous
#include <cuda_runtime.h>
#include <cuda_fp16.h>

#define B_   4
#define CIN  256
#define CO_  64
#define N_   576   // 24*24
#define CV_  256

// Scratch (device globals — no allocation allowed)
__device__ float g_kp[B_ * N_ * CO_];          // (B, Nk, CO)
__device__ float g_qp[B_ * N_ * CO_];          // (B, Nq, CO)
__device__ float g_attn[B_ * N_ * N_];         // (B, Nk, Nq)

// ---------- packed helpers ----------
__device__ __forceinline__ unsigned long long pack2(float lo, float hi) {
    unsigned long long r;
    asm("mov.b64 %0, {%1, %2};" : "=l"(r) : "f"(lo), "f"(hi));
    return r;
}
__device__ __forceinline__ void unpack2(unsigned long long v, float& lo, float& hi) {
    asm("mov.b64 {%0, %1}, %2;" : "=f"(lo), "=f"(hi) : "l"(v));
}
__device__ __forceinline__ unsigned long long ffma2(unsigned long long a,
                                                    unsigned long long b,
                                                    unsigned long long c) {
    unsigned long long d;
    asm("fma.rn.f32x2 %0, %1, %2, %3;" : "=l"(d) : "l"(a), "l"(b), "l"(c));
    return d;
}
__device__ __forceinline__ float tanhfast(float x) {
    float y;
    asm("tanh.approx.f32 %0, %1;" : "=f"(y) : "f"(x));
    return y;
}
__device__ __forceinline__ unsigned tanh_h2(unsigned x) {
    unsigned y;
    asm("tanh.approx.f16x2 %0, %1;" : "=r"(y) : "r"(x));
    return y;
}
__device__ __forceinline__ __half2 u2h(unsigned u) { return *(__half2*)&u; }
__device__ __forceinline__ unsigned h2u(__half2 h) { return *(unsigned*)&h; }

// ============================================================================
// Kernel A: projections. out[b,n,c] = sum_ch X[b,ch,n]*W[c,ch] + bias[c]
// grid (18 n-tiles of 32, B, 2), 256 thr; thread = 2c x 4n.
// ENTIRE K-dim staged once (X 32KB + W 67.6KB dynamic smem), ONE barrier,
// then a single 256-iter FFMA2 loop. No per-chunk latency exposure.
// ============================================================================
#define PROJ_SMEM_BYTES ((256 * 32 + 256 * 66) * 4)

__global__ void __launch_bounds__(256) proj_kernel(
    const float* __restrict__ key, const float* __restrict__ query,
    const float* __restrict__ Wk,  const float* __restrict__ bk,
    const float* __restrict__ Wq,  const float* __restrict__ bq)
{
    extern __shared__ float smem[];
    float (*sX)[32] = (float (*)[32])smem;               // [256 ch][32 n]
    float (*sW)[66] = (float (*)[66])(smem + 256 * 32);  // [256 ch][64 c] (stride 66)

    const int kind = blockIdx.z;
    const float* X    = kind ? query : key;    // (B, CIN, N)
    const float* W    = kind ? Wq    : Wk;     // (CO, CIN)
    const float* bias = kind ? bq    : bk;
    float* outp       = kind ? g_qp  : g_kp;   // (B, N, CO)

    const int b  = blockIdx.y;
    const int n0 = blockIdx.x * 32;
    const int t  = threadIdx.x;

    // ---- stage X: 256ch x 32n as float4 (coalesced; 8 LDG.128/thread) ----
    {
        const int n4  = (t & 7) * 4;
        const int chb = t >> 3;                  // 0..31
        #pragma unroll
        for (int i = 0; i < 8; i++) {
            const int ch = chb + i * 32;
            *(float4*)&sX[ch][n4] =
                *(const float4*)&X[((size_t)(b * CIN + ch)) * N_ + n0 + n4];
        }
    }
    // ---- stage W transposed: sW[ch][c]; thread t owns ch=t (coalesced LDG,
    //      STS banks (2*ch+c)%32 -> 2-way only) ----
    {
        #pragma unroll 16
        for (int cr = 0; cr < 64; cr++)
            sW[t][cr] = W[cr * CIN + t];
    }
    __syncthreads();

    // ---- compute: thread = 2c x 4n ----
    const int ng = t & 7;            // n = ng*4 .. +3
    const int c  = (t >> 3) * 2;     // c, c+1

    unsigned long long a00 = 0ull, a01 = 0ull, a10 = 0ull, a11 = 0ull;

    #pragma unroll 8
    for (int ch = 0; ch < CIN; ch++) {
        const ulonglong2 xp = *(const ulonglong2*)&sX[ch][ng * 4];  // 2 n-pairs
        const float2     w2 = *(const float2*)&sW[ch][c];           // 2 c
        const unsigned long long ww0 = pack2(w2.x, w2.x);
        const unsigned long long ww1 = pack2(w2.y, w2.y);
        a00 = ffma2(xp.x, ww0, a00);
        a01 = ffma2(xp.y, ww0, a01);
        a10 = ffma2(xp.x, ww1, a10);
        a11 = ffma2(xp.y, ww1, a11);
    }

    const float bv0 = bias[c];
    const float bv1 = bias[c + 1];
    float x0, x1, x2, x3, y0, y1, y2, y3;
    unpack2(a00, x0, x1);   // c,   n0..n1
    unpack2(a01, x2, x3);   // c,   n2..n3
    unpack2(a10, y0, y1);   // c+1, n0..n1
    unpack2(a11, y2, y3);   // c+1, n2..n3

    const int n = n0 + ng * 4;
    float* op = outp + ((size_t)b * N_ + n) * CO_ + c;
    *(float2*)(op + 0 * CO_) = make_float2(x0 + bv0, y0 + bv1);
    *(float2*)(op + 1 * CO_) = make_float2(x1 + bv0, y1 + bv1);
    *(float2*)(op + 2 * CO_) = make_float2(x2 + bv0, y2 + bv1);
    *(float2*)(op + 3 * CO_) = make_float2(x3 + bv0, y3 + bv1);
}

// ============================================================================
// Kernel B: attn[b,k,q] = sigmoid( bf + sum_c tanh(kp[k,c]+qp[q,c])*wf[c] )
// grid (18 q-tiles, 18 k-tiles, B), 256 thr. Thread = 4k x 1q (q = lane).
// (unchanged from R4)
// ============================================================================
__global__ void __launch_bounds__(256) attn_kernel(
    const float* __restrict__ wf, const float* __restrict__ bfp)
{
    const int b  = blockIdx.z;
    const int k0 = blockIdx.y * 32;
    const int q0 = blockIdx.x * 32;

    __shared__ unsigned skh[32][34];   // half2 pairs over c
    __shared__ unsigned sqh[32][34];
    __shared__ unsigned swh[32];

    const int t = threadIdx.x;
    #pragma unroll
    for (int j = 0; j < 4; j++) {
        const int idx = t + j * 256;       // 1024 half2 per tile
        const int r  = idx >> 5;
        const int cc = idx & 31;
        const float2 kv = *(const float2*)&g_kp[((size_t)b * N_ + k0 + r) * CO_ + cc * 2];
        const float2 qv = *(const float2*)&g_qp[((size_t)b * N_ + q0 + r) * CO_ + cc * 2];
        skh[r][cc] = h2u(__floats2half2_rn(kv.x, kv.y));
        sqh[r][cc] = h2u(__floats2half2_rn(qv.x, qv.y));
    }
    if (t < 32) {
        const float2 w = *(const float2*)&wf[t * 2];
        swh[t] = h2u(__floats2half2_rn(w.x, w.y));
    }
    __syncthreads();

    const int q  = t & 31;            // lane -> CF q loads, coalesced STG
    const int k4 = (t >> 5) * 4;      // 4 k's (warp-constant -> broadcast)

    __half2 ae[4], ao[4];
    #pragma unroll
    for (int i = 0; i < 4; i++) { ae[i] = __float2half2_rn(0.f); ao[i] = ae[i]; }

    const unsigned* __restrict__ qrow = sqh[q];

    #pragma unroll
    for (int cc = 0; cc < 32; cc += 2) {
        const uint2 qv = *(const uint2*)&qrow[cc];
        const uint2 wv = *(const uint2*)&swh[cc];
        #pragma unroll
        for (int i = 0; i < 4; i++) {
            const uint2 kv = *(const uint2*)&skh[k4 + i][cc];
            const unsigned t0 = tanh_h2(h2u(__hadd2(u2h(kv.x), u2h(qv.x))));
            const unsigned t1 = tanh_h2(h2u(__hadd2(u2h(kv.y), u2h(qv.y))));
            ae[i] = __hfma2(u2h(t0), u2h(wv.x), ae[i]);
            ao[i] = __hfma2(u2h(t1), u2h(wv.y), ao[i]);
        }
    }

    const float bf = __ldg(bfp);
    #pragma unroll
    for (int i = 0; i < 4; i++) {
        const float2 fe = __half22float2(ae[i]);
        const float2 fo = __half22float2(ao[i]);
        const float s = bf + ((fe.x + fe.y) + (fo.x + fo.y));
        g_attn[((size_t)b * N_ + k0 + k4 + i) * N_ + q0 + q] =
            fmaf(0.5f, tanhfast(0.5f * s), 0.5f);   // sigmoid
    }
}

// ============================================================================
// Kernel C: out[b,c,q] = sum_k value[b,c,k] * attn[b,k,q]
// grid (9 q-tiles of 64, 4 c-tiles of 64, B), 256 thr; thread = 4c x 4q.
// (unchanged from R4)
// ============================================================================
__global__ void __launch_bounds__(256) out_kernel(
    const float* __restrict__ value, float* __restrict__ out)
{
    const int b  = blockIdx.z;
    const int c0 = blockIdx.y * 64;
    const int q0 = blockIdx.x * 64;

    __shared__ __align__(16) float sV[32][68];   // [k][c]
    __shared__ __align__(16) float sA[32][68];   // [k][q]

    const int t  = threadIdx.x;
    const int qg = t & 15;          // q = qg*4 .. +3
    const int cg = t >> 4;          // c = cg*4 .. +3

    unsigned long long acc[4][2];
    #pragma unroll
    for (int i = 0; i < 4; i++) { acc[i][0] = 0ull; acc[i][1] = 0ull; }

    for (int k0 = 0; k0 < N_; k0 += 32) {
        {   // V tile 64c x 32k, transpose into sV[k][c] (coalesced over k)
            const int kk = t & 31;
            const int cb = t >> 5;
            #pragma unroll
            for (int i = 0; i < 8; i++) {
                const int cr = cb + i * 8;
                sV[kk][cr] = value[((size_t)(b * CV_ + c0 + cr)) * N_ + k0 + kk];
            }
        }
        {   // A tile 32k x 64q (coalesced over q)
            const int q  = t & 63;
            const int kb = t >> 6;
            #pragma unroll
            for (int i = 0; i < 8; i++) {
                const int kr = kb + i * 4;
                sA[kr][q] = g_attn[((size_t)b * N_ + k0 + kr) * N_ + q0 + q];
            }
        }
        __syncthreads();

        #pragma unroll 8
        for (int kk = 0; kk < 32; kk++) {
            const float4 v4 = *(const float4*)&sV[kk][cg * 4];         // 4 c
            const ulonglong2 a2 = *(const ulonglong2*)&sA[kk][qg * 4]; // 4 q
            const unsigned long long v0 = pack2(v4.x, v4.x);
            const unsigned long long v1 = pack2(v4.y, v4.y);
            const unsigned long long v2 = pack2(v4.z, v4.z);
            const unsigned long long v3 = pack2(v4.w, v4.w);
            acc[0][0] = ffma2(v0, a2.x, acc[0][0]);
            acc[0][1] = ffma2(v0, a2.y, acc[0][1]);
            acc[1][0] = ffma2(v1, a2.x, acc[1][0]);
            acc[1][1] = ffma2(v1, a2.y, acc[1][1]);
            acc[2][0] = ffma2(v2, a2.x, acc[2][0]);
            acc[2][1] = ffma2(v2, a2.y, acc[2][1]);
            acc[3][0] = ffma2(v3, a2.x, acc[3][0]);
            acc[3][1] = ffma2(v3, a2.y, acc[3][1]);
        }
        __syncthreads();
    }

    #pragma unroll
    for (int i = 0; i < 4; i++) {
        float o0, o1, o2, o3;
        unpack2(acc[i][0], o0, o1);
        unpack2(acc[i][1], o2, o3);
        *(float4*)&out[((size_t)(b * CV_ + c0 + cg * 4 + i)) * N_ + q0 + qg * 4] =
            make_float4(o0, o1, o2, o3);
    }
}

// ============================================================================
extern "C" void kernel_launch(void* const* d_in, const int* in_sizes, int n_in,
                              void* d_out, int out_size)
{
    const float* key   = (const float*)d_in[0];
    const float* query = (const float*)d_in[1];
    const float* value = (const float*)d_in[2];
    const float* Wk    = (const float*)d_in[3];
    const float* bk    = (const float*)d_in[4];
    const float* Wq    = (const float*)d_in[5];
    const float* bq    = (const float*)d_in[6];
    const float* wf    = (const float*)d_in[7];
    const float* bf    = (const float*)d_in[8];
    float* out = (float*)d_out;

    static int smem_set = 0;
    if (!smem_set) {
        cudaFuncSetAttribute(proj_kernel,
                             cudaFuncAttributeMaxDynamicSharedMemorySize,
                             PROJ_SMEM_BYTES);
        smem_set = 1;
    }

    proj_kernel<<<dim3(N_ / 32, B_, 2), 256, PROJ_SMEM_BYTES>>>(key, query, Wk, bk, Wq, bq);
    attn_kernel<<<dim3(N_ / 32, N_ / 32, B_), 256>>>(wf, bf);
    out_kernel<<<dim3(N_ / 64, CV_ / 64, B_), 256>>>(value, out);
}